// round 6
// baseline (speedup 1.0000x reference)
#include <cuda_runtime.h>
#include <cstdint>

#define NN 50000
#define EE 800000
#define DD 512
#define NV4 (DD/4)
#define LOFF ((size_t)2048 * 512)

// ---------------- static scratch (no allocations allowed) ----------------
__device__ float g_s1[(size_t)NN * DD];
__device__ float g_s2[(size_t)NN * DD];
__device__ float g_m1[(size_t)NN * DD];
__device__ float g_m2[(size_t)NN * DD];
__device__ float g_l1[(size_t)NN * DD];
__device__ float g_l2[(size_t)NN * DD];
__device__ float g_aggs[(size_t)NN * DD];   // segment sum
__device__ float g_aggm[(size_t)NN * DD];   // segment max
__device__ float g_z[(size_t)4 * NN * DD];  // z planes (plane 0 reused for cat out)
__device__ float g_bprep[2 * LOFF];         // transposed tf32 hi/lo weights (8MB)
__device__ int   g_deg[NN];
__device__ int   g_rowp[NN + 1];
__device__ int   g_cur[NN];
__device__ int   g_csrc[EE];
__device__ float g_invdeg[NN];
__device__ float g_csum[4 * DD];
__device__ float g_csqr[4 * DD];
__device__ float g_scale[4 * DD];
__device__ float g_shift[4 * DD];

// ---------------- PTX helpers (sm_80-generic only) ----------------
__device__ __forceinline__ uint32_t smem_u32(const void* p) {
    uint32_t a;
    asm("{ .reg .u64 t; cvta.to.shared.u64 t, %1; cvt.u32.u64 %0, t; }" : "=r"(a) : "l"(p));
    return a;
}
__device__ __forceinline__ void cp_async16(uint32_t saddr, const void* gaddr, int sz) {
    asm volatile("cp.async.cg.shared.global [%0], [%1], 16, %2;"
                 :: "r"(saddr), "l"(gaddr), "r"(sz));
}
__device__ __forceinline__ void cp_commit() {
    asm volatile("cp.async.commit_group;");
}
template <int N>
__device__ __forceinline__ void cp_wait() {
    asm volatile("cp.async.wait_group %0;" :: "n"(N));
}
__device__ __forceinline__ void ldsm_x4(uint32_t& r0, uint32_t& r1, uint32_t& r2,
                                        uint32_t& r3, uint32_t addr) {
    asm volatile("ldmatrix.sync.aligned.m8n8.x4.shared.b16 {%0,%1,%2,%3}, [%4];"
                 : "=r"(r0), "=r"(r1), "=r"(r2), "=r"(r3) : "r"(addr));
}
__device__ __forceinline__ uint32_t f2tf32(uint32_t x) {
    uint32_t d;
    asm("cvt.rna.tf32.f32 %0, %1;" : "=r"(d) : "f"(__uint_as_float(x)));
    return d;
}
__device__ __forceinline__ void mma_tf32(float* c, const uint32_t* a, const uint32_t* b) {
    asm volatile(
        "mma.sync.aligned.m16n8k8.row.col.f32.tf32.tf32.f32 "
        "{%0,%1,%2,%3}, {%4,%5,%6,%7}, {%8,%9}, {%0,%1,%2,%3};"
        : "+f"(c[0]), "+f"(c[1]), "+f"(c[2]), "+f"(c[3])
        : "r"(a[0]), "r"(a[1]), "r"(a[2]), "r"(a[3]), "r"(b[0]), "r"(b[1]));
}

// ---------------- CSR build ----------------
__global__ void k_count(const int* __restrict__ dst, int E) {
    int e = blockIdx.x * blockDim.x + threadIdx.x;
    if (e < E) atomicAdd(&g_deg[dst[e]], 1);
}

__global__ void k_scan(int M) {
    __shared__ int sh[1024];
    __shared__ int running;
    if (threadIdx.x == 0) running = 0;
    __syncthreads();
    for (int base = 0; base < M; base += 1024) {
        int i = base + threadIdx.x;
        int v = (i < M) ? g_deg[i] : 0;
        sh[threadIdx.x] = v;
        __syncthreads();
        for (int off = 1; off < 1024; off <<= 1) {
            int t = 0;
            if ((int)threadIdx.x >= off) t = sh[threadIdx.x - off];
            __syncthreads();
            sh[threadIdx.x] += t;
            __syncthreads();
        }
        int incl = sh[threadIdx.x];
        int excl = running + incl - v;
        if (i < M) {
            g_rowp[i] = excl;
            g_cur[i] = excl;
            g_invdeg[i] = 1.0f / (float)(v > 1 ? v : 1);
        }
        __syncthreads();
        if (threadIdx.x == 0) running += sh[1023];
        __syncthreads();
    }
    if (threadIdx.x == 0) g_rowp[M] = running;
}

__global__ void k_scatter(const int* __restrict__ src, const int* __restrict__ dst, int E) {
    int e = blockIdx.x * blockDim.x + threadIdx.x;
    if (e < E) {
        int d = dst[e];
        int p = atomicAdd(&g_cur[d], 1);
        g_csrc[p] = src[e];
    }
}

// ---------------- aggregation: one block (128 thr) per node ----------------
__global__ void k_aggregate(const float* __restrict__ X) {
    int nid = blockIdx.x;
    int t = threadIdx.x;
    int beg = g_rowp[nid], end = g_rowp[nid + 1];
    float4 s = make_float4(0.f, 0.f, 0.f, 0.f);
    float4 m = make_float4(-3.4e38f, -3.4e38f, -3.4e38f, -3.4e38f);
    const float4* Xb = (const float4*)X;
    for (int e = beg; e < end; e++) {
        int r = __ldg(&g_csrc[e]);
        float4 v = __ldg(Xb + (size_t)r * NV4 + t);
        s.x += v.x; s.y += v.y; s.z += v.z; s.w += v.w;
        m.x = fmaxf(m.x, v.x); m.y = fmaxf(m.y, v.y);
        m.z = fmaxf(m.z, v.z); m.w = fmaxf(m.w, v.w);
    }
    if (beg == end) m = make_float4(0.f, 0.f, 0.f, 0.f);
    ((float4*)g_aggs)[(size_t)nid * NV4 + t] = s;
    ((float4*)g_aggm)[(size_t)nid * NV4 + t] = m;
}

// -------- weight prep: transpose [K][N] -> [N][K] + tf32 hi/lo split --------
__global__ void k_prep(const float* __restrict__ W, float* __restrict__ out, int K, int N) {
    __shared__ float t[32][33];
    const float* Wp = W + (size_t)blockIdx.z * K * N;
    float* op = out + (size_t)blockIdx.z * K * N;
    int k0 = blockIdx.x * 32;
    int n0 = blockIdx.y * 32;
    int tx = threadIdx.x & 31, ty = threadIdx.x >> 5;
    for (int r = ty; r < 32; r += 8)
        t[r][tx] = __ldg(Wp + (size_t)(k0 + r) * N + n0 + tx);
    __syncthreads();
    for (int r = ty; r < 32; r += 8) {
        float w = t[tx][r];
        uint32_t hi = f2tf32(__float_as_uint(w));
        float lof = w - __uint_as_float(hi);
        uint32_t lo = f2tf32(__float_as_uint(lof));
        size_t o = (size_t)(n0 + r) * K + k0 + tx;
        op[o] = __uint_as_float(hi);
        op[LOFF + o] = __uint_as_float(lo);
    }
}

// ---------------- 3xTF32 mma.sync GEMM ----------------
// CTA 128x256, 8 warps (2m x 4n), warp 64x64, BK=32 double-buffered cp.async.
// mode 0: z[plane] = A_plane @ W[plane]^T-prep (K=512), plane=blockIdx.z
// mode 1: z[0]     = [m1|m2|l1|l2] @ catW-prep (K=2048)
#define ASTRIDE 36
#define ABUF (128 * ASTRIDE)
#define BBUF (256 * ASTRIDE)
#define SMEM_GEMM ((2 * ABUF + 4 * BBUF) * 4)

__global__ void __launch_bounds__(256, 1)
k_gemm_mma(const float* __restrict__ A0, const float* __restrict__ Bt,
           const float* __restrict__ bias, int M, int mode) {
    extern __shared__ float sm[];
    float* Abufs = sm;                  // 2 * ABUF
    float* Bbufs = sm + 2 * ABUF;       // 2 * (BBUF hi + BBUF lo)
    const int tid = threadIdx.x;
    const int wid = tid >> 5, lane = tid & 31;
    const int wm = wid & 1, wn = wid >> 1;
    const int rowBase = blockIdx.x * 128;
    const int colBase = blockIdx.y * 256;
    const int plane = blockIdx.z;

    const int K = (mode == 0) ? 512 : 2048;
    const int nStages = K / 32;
    const int ldb = K;
    const float* Bbase = Bt + ((mode == 0) ? (size_t)plane * 512 * 512 : 0);

    // ---- async loaders ----
    auto loadA = [&](int s) {
        int k0 = s * 32;
        const float* Ap;
        int kin;
        if (mode == 0) {
            Ap = (plane == 0) ? A0 : ((plane == 3) ? g_aggm : g_aggs);
            kin = k0;
        } else {
            int seg = k0 >> 9;
            Ap = (seg == 0) ? g_m1 : (seg == 1) ? g_m2 : (seg == 2) ? g_l1 : g_l2;
            kin = k0 & 511;
        }
        float* Ab = Abufs + (s & 1) * ABUF;
#pragma unroll
        for (int i = 0; i < 4; i++) {
            int idx = tid + 256 * i;
            int r = idx >> 3, f4 = idx & 7;
            int grow = rowBase + r;
            int ok = (grow < M) ? 16 : 0;
            int gr = (grow < M) ? grow : (M - 1);
            cp_async16(smem_u32(Ab + r * ASTRIDE + f4 * 4),
                       Ap + (size_t)gr * 512 + kin + f4 * 4, ok);
        }
    };
    auto loadB = [&](int s) {
        int k0 = s * 32;
        float* Bh = Bbufs + (s & 1) * (2 * BBUF);
        float* Bl = Bh + BBUF;
#pragma unroll
        for (int i = 0; i < 8; i++) {
            int idx = tid + 256 * i;
            int r = idx >> 3, f4 = idx & 7;
            const float* gsrc = Bbase + (size_t)(colBase + r) * ldb + k0 + f4 * 4;
            cp_async16(smem_u32(Bh + r * ASTRIDE + f4 * 4), gsrc, 16);
            cp_async16(smem_u32(Bl + r * ASTRIDE + f4 * 4), gsrc + LOFF, 16);
        }
    };

    float c[4][8][4];
#pragma unroll
    for (int mi = 0; mi < 4; mi++)
#pragma unroll
        for (int ni = 0; ni < 8; ni++)
#pragma unroll
            for (int j = 0; j < 4; j++) c[mi][ni][j] = 0.f;

    loadA(0); loadB(0); cp_commit();
    loadA(1); loadB(1); cp_commit();

    const int sub = lane >> 3, lr = lane & 7;
    const int aRowOff = (sub & 1) * 8 + lr;     // within 16-row tile
    const int aColOff = (sub >> 1) * 4;         // float col half
    const int bRowOff = (sub >> 1) * 8 + lr;    // within 16-n tile
    const int bColOff = (sub & 1) * 4;

    for (int s = 0; s < nStages; s++) {
        if (s + 1 < nStages) cp_wait<1>(); else cp_wait<0>();
        __syncthreads();
        uint32_t aBase = smem_u32(Abufs + (s & 1) * ABUF);
        uint32_t bHiBase = smem_u32(Bbufs + (s & 1) * (2 * BBUF));
        uint32_t bLoBase = bHiBase + BBUF * 4;
#pragma unroll
        for (int k8 = 0; k8 < 4; k8++) {
            uint32_t ah[4][4], al[4][4];
#pragma unroll
            for (int mi = 0; mi < 4; mi++) {
                int row = wm * 64 + mi * 16 + aRowOff;
                uint32_t ad = aBase + (uint32_t)(row * ASTRIDE + k8 * 8 + aColOff) * 4;
                uint32_t r0, r1, r2, r3;
                ldsm_x4(r0, r1, r2, r3, ad);
                uint32_t rr[4] = {r0, r1, r2, r3};
#pragma unroll
                for (int j = 0; j < 4; j++) {
                    uint32_t hi = f2tf32(rr[j]);
                    float lof = __uint_as_float(rr[j]) - __uint_as_float(hi);
                    ah[mi][j] = hi;
                    al[mi][j] = f2tf32(__float_as_uint(lof));
                }
            }
#pragma unroll
            for (int np = 0; np < 4; np++) {
                int row = wn * 64 + np * 16 + bRowOff;
                uint32_t off = (uint32_t)(row * ASTRIDE + k8 * 8 + bColOff) * 4;
                uint32_t h0, h1, h2, h3, l0, l1, l2, l3;
                ldsm_x4(h0, h1, h2, h3, bHiBase + off);
                ldsm_x4(l0, l1, l2, l3, bLoBase + off);
                uint32_t bh0[2] = {h0, h1}, bh1[2] = {h2, h3};
                uint32_t bl0[2] = {l0, l1}, bl1[2] = {l2, l3};
#pragma unroll
                for (int mi = 0; mi < 4; mi++) {
                    mma_tf32(c[mi][2 * np],     ah[mi], bh0);
                    mma_tf32(c[mi][2 * np],     al[mi], bh0);
                    mma_tf32(c[mi][2 * np],     ah[mi], bl0);
                    mma_tf32(c[mi][2 * np + 1], ah[mi], bh1);
                    mma_tf32(c[mi][2 * np + 1], al[mi], bh1);
                    mma_tf32(c[mi][2 * np + 1], ah[mi], bl1);
                }
            }
        }
        __syncthreads();
        if (s + 2 < nStages) { loadA(s + 2); loadB(s + 2); cp_commit(); }
    }

    // ---- epilogue ----
    const float* bp = bias + ((mode == 0) ? plane * DD : 0);
    float* zbase = (mode == 0) ? (g_z + (size_t)plane * M * DD) : g_z;
    const int doScale = (mode == 0 && plane == 2);
#pragma unroll
    for (int mi = 0; mi < 4; mi++) {
        int row0 = rowBase + wm * 64 + mi * 16 + (lane >> 2);
        int row1 = row0 + 8;
        float rs0 = 1.f, rs1 = 1.f;
        if (doScale) {
            if (row0 < M) rs0 = g_invdeg[row0];
            if (row1 < M) rs1 = g_invdeg[row1];
        }
#pragma unroll
        for (int ni = 0; ni < 8; ni++) {
            int col = colBase + wn * 64 + ni * 8 + (lane & 3) * 2;
            float b0 = __ldg(bp + col), b1 = __ldg(bp + col + 1);
            if (row0 < M) {
                float2 v;
                v.x = fmaf(c[mi][ni][0], rs0, b0);
                v.y = fmaf(c[mi][ni][1], rs0, b1);
                *(float2*)(zbase + (size_t)row0 * DD + col) = v;
            }
            if (row1 < M) {
                float2 v;
                v.x = fmaf(c[mi][ni][2], rs1, b0);
                v.y = fmaf(c[mi][ni][3], rs1, b1);
                *(float2*)(zbase + (size_t)row1 * DD + col) = v;
            }
        }
    }
}

// ---------------- per-(k,d) stats over nodes ----------------
__global__ void k_stats(int M) {
    int k = blockIdx.x >> 2;
    int d = ((blockIdx.x & 3) << 7) + threadIdx.x;
    int rows = (M + gridDim.y - 1) / gridDim.y;
    int r0 = blockIdx.y * rows;
    int r1 = r0 + rows; if (r1 > M) r1 = M;
    const float* p = g_z + ((size_t)k * M) * DD + d;
    float s = 0.f, q = 0.f;
    for (int r = r0; r < r1; r++) {
        float v = __ldg(p + (size_t)r * DD);
        s += v;
        q = fmaf(v, v, q);
    }
    atomicAdd(&g_csum[k * DD + d], s);
    atomicAdd(&g_csqr[k * DD + d], q);
}

__global__ void k_finalize(const float* __restrict__ gam, const float* __restrict__ bet,
                           int M, int P) {
    int i = blockIdx.x * blockDim.x + threadIdx.x;
    if (i < P * DD) {
        float inv = 1.0f / (float)M;
        float mu = g_csum[i] * inv;
        float var = g_csqr[i] * inv - mu * mu;
        float sc = rsqrtf(var + 1e-5f) * gam[i];
        g_scale[i] = sc;
        g_shift[i] = bet[i] - mu * sc;
    }
}

// ---------------- weighted relu combine over k ----------------
__global__ void k_combine(const float* __restrict__ w, float* __restrict__ out,
                          int M, int acc) {
    int idx = blockIdx.x * blockDim.x + threadIdx.x;
    int total = M * NV4;
    if (idx >= total) return;
    int dc = (idx % NV4) * 4;
    float4 r = acc ? ((const float4*)out)[idx] : make_float4(0.f, 0.f, 0.f, 0.f);
#pragma unroll
    for (int k = 0; k < 4; k++) {
        float wk = __ldg(w + k);
        float4 v = __ldg((const float4*)g_z + (size_t)k * M * NV4 + idx);
        float4 sc = *(const float4*)&g_scale[k * DD + dc];
        float4 sh = *(const float4*)&g_shift[k * DD + dc];
        float e;
        e = fmaxf(fmaf(v.x, sc.x, sh.x), 0.f); r.x = fmaf(wk, e, r.x);
        e = fmaxf(fmaf(v.y, sc.y, sh.y), 0.f); r.y = fmaf(wk, e, r.y);
        e = fmaxf(fmaf(v.z, sc.z, sh.z), 0.f); r.z = fmaf(wk, e, r.z);
        e = fmaxf(fmaf(v.w, sc.w, sh.w), 0.f); r.w = fmaf(wk, e, r.w);
    }
    ((float4*)out)[idx] = r;
}

// ---------------- final residual + BN + relu ----------------
__global__ void k_final(const float* __restrict__ h, float* __restrict__ out, int M) {
    int idx = blockIdx.x * blockDim.x + threadIdx.x;
    int total = M * NV4;
    if (idx >= total) return;
    int dc = (idx % NV4) * 4;
    float4 v = ((const float4*)g_z)[idx];
    float4 sc = *(const float4*)&g_scale[dc];
    float4 sh = *(const float4*)&g_shift[dc];
    float4 hv = ((const float4*)h)[idx];
    float4 o;
    o.x = hv.x + fmaxf(fmaf(v.x, sc.x, sh.x), 0.f);
    o.y = hv.y + fmaxf(fmaf(v.y, sc.y, sh.y), 0.f);
    o.z = hv.z + fmaxf(fmaf(v.z, sc.z, sh.z), 0.f);
    o.w = hv.w + fmaxf(fmaf(v.w, sc.w, sh.w), 0.f);
    ((float4*)out)[idx] = o;
}

// ---------------- host orchestration ----------------
static void run_mixed(const float* X, const float* W4, const float* b4,
                      const float* g4, const float* be4, const float* w4,
                      float* outp, int acc, int M, void* sump, void* sqrp,
                      const float* bprep) {
    k_prep<<<dim3(16, 16, 4), 256>>>(W4, (float*)bprep, 512, 512);
    cudaMemsetAsync(sump, 0, 4 * DD * sizeof(float));
    cudaMemsetAsync(sqrp, 0, 4 * DD * sizeof(float));
    k_gemm_mma<<<dim3((M + 127) / 128, 2, 4), 256, SMEM_GEMM>>>(X, bprep, b4, M, 0);
    k_stats<<<dim3(16, 128), 128>>>(M);
    k_finalize<<<8, 256>>>(g4, be4, M, 4);
    k_combine<<<(M * NV4 + 255) / 256, 256>>>(w4, outp, M, acc);
}

extern "C" void kernel_launch(void* const* d_in, const int* in_sizes, int n_in,
                              void* d_out, int out_size) {
    const float* h    = (const float*)d_in[0];
    const int*   src  = (const int*)d_in[1];
    const int*   dst  = (const int*)d_in[2];
    const float* wf   = (const float*)d_in[3];
    const float* wm   = (const float*)d_in[4];
    const float* wl   = (const float*)d_in[5];
    const float* pfW  = (const float*)d_in[6];
    const float* pfb  = (const float*)d_in[7];
    const float* pfg  = (const float*)d_in[8];
    const float* pfB  = (const float*)d_in[9];
    const float* pmW  = (const float*)d_in[10];
    const float* pmb  = (const float*)d_in[11];
    const float* pmg  = (const float*)d_in[12];
    const float* pmB  = (const float*)d_in[13];
    const float* plW  = (const float*)d_in[14];
    const float* plb  = (const float*)d_in[15];
    const float* plg  = (const float*)d_in[16];
    const float* plB  = (const float*)d_in[17];
    const float* catW = (const float*)d_in[18];
    const float* catb = (const float*)d_in[19];
    const float* bng  = (const float*)d_in[20];
    const float* bnb  = (const float*)d_in[21];

    int M = in_sizes[0] / DD;
    int E = in_sizes[1];
    float* out = (float*)d_out;

    cudaFuncSetAttribute(k_gemm_mma, cudaFuncAttributeMaxDynamicSharedMemorySize, SMEM_GEMM);

    void *s1, *s2, *m1, *m2, *l1, *l2, *degp, *sump, *sqrp, *bprep;
    cudaGetSymbolAddress(&s1, g_s1);
    cudaGetSymbolAddress(&s2, g_s2);
    cudaGetSymbolAddress(&m1, g_m1);
    cudaGetSymbolAddress(&m2, g_m2);
    cudaGetSymbolAddress(&l1, g_l1);
    cudaGetSymbolAddress(&l2, g_l2);
    cudaGetSymbolAddress(&degp, g_deg);
    cudaGetSymbolAddress(&sump, g_csum);
    cudaGetSymbolAddress(&sqrp, g_csqr);
    cudaGetSymbolAddress(&bprep, g_bprep);

    const size_t slabW = (size_t)4 * DD * DD;
    const size_t slabB = 4 * DD;

    // CSR build (shared by all aggregations this launch)
    cudaMemsetAsync(degp, 0, M * sizeof(int));
    k_count<<<(E + 255) / 256, 256>>>(dst, E);
    k_scan<<<1, 1024>>>(M);
    k_scatter<<<(E + 255) / 256, 256>>>(src, dst, E);

    // first block: s1 = mixed(wf0, h); s2 = mixed(wf1, h) + mixed(wf2, s1)
    k_aggregate<<<M, 128>>>(h);
    run_mixed(h, pfW + 0 * slabW, pfb + 0 * slabB, pfg + 0 * slabB, pfB + 0 * slabB,
              wf + 0, (float*)s1, 0, M, sump, sqrp, (const float*)bprep);
    run_mixed(h, pfW + 1 * slabW, pfb + 1 * slabB, pfg + 1 * slabB, pfB + 1 * slabB,
              wf + 4, (float*)s2, 0, M, sump, sqrp, (const float*)bprep);
    k_aggregate<<<M, 128>>>((const float*)s1);
    run_mixed((const float*)s1, pfW + 2 * slabW, pfb + 2 * slabB, pfg + 2 * slabB,
              pfB + 2 * slabB, wf + 8, (float*)s2, 1, M, sump, sqrp, (const float*)bprep);
    // middle (agg(s1) still valid): m1 = mixed(wm0, s1)
    run_mixed((const float*)s1, pmW + 0 * slabW, pmb + 0 * slabB, pmg + 0 * slabB,
              pmB + 0 * slabB, wm + 0, (float*)m1, 0, M, sump, sqrp, (const float*)bprep);
    k_aggregate<<<M, 128>>>((const float*)s2);
    run_mixed((const float*)s2, pmW + 1 * slabW, pmb + 1 * slabB, pmg + 1 * slabB,
              pmB + 1 * slabB, wm + 4, (float*)m2, 0, M, sump, sqrp, (const float*)bprep);
    // last block
    k_aggregate<<<M, 128>>>((const float*)m1);
    run_mixed((const float*)m1, plW + 0 * slabW, plb + 0 * slabB, plg + 0 * slabB,
              plB + 0 * slabB, wl + 0, (float*)l1, 0, M, sump, sqrp, (const float*)bprep);
    run_mixed((const float*)m1, plW + 2 * slabW, plb + 2 * slabB, plg + 2 * slabB,
              plB + 2 * slabB, wl + 8, (float*)l2, 0, M, sump, sqrp, (const float*)bprep);
    k_aggregate<<<M, 128>>>((const float*)m2);
    run_mixed((const float*)m2, plW + 1 * slabW, plb + 1 * slabB, plg + 1 * slabB,
              plB + 1 * slabB, wl + 4, (float*)l1, 1, M, sump, sqrp, (const float*)bprep);
    run_mixed((const float*)m2, plW + 3 * slabW, plb + 3 * slabB, plg + 3 * slabB,
              plB + 3 * slabB, wl + 12, (float*)l2, 1, M, sump, sqrp, (const float*)bprep);
    k_aggregate<<<M, 128>>>((const float*)l1);
    run_mixed((const float*)l1, plW + 4 * slabW, plb + 4 * slabB, plg + 4 * slabB,
              plB + 4 * slabB, wl + 16, (float*)l2, 1, M, sump, sqrp, (const float*)bprep);

    // cat GEMM + batchnorm + relu + residual
    k_prep<<<dim3(64, 16, 1), 256>>>(catW, (float*)bprep, 2048, 512);
    k_gemm_mma<<<dim3((M + 127) / 128, 2, 1), 256, SMEM_GEMM>>>(h, (const float*)bprep, catb, M, 1);
    cudaMemsetAsync(sump, 0, 4 * DD * sizeof(float));
    cudaMemsetAsync(sqrp, 0, 4 * DD * sizeof(float));
    k_stats<<<dim3(4, 128), 128>>>(M);
    k_finalize<<<8, 256>>>(bng, bnb, M, 1);
    k_final<<<(M * NV4 + 255) / 256, 256>>>(h, out, M);
}

// round 7
// speedup vs baseline: 2.3524x; 2.3524x over previous
#include <cuda_runtime.h>
#include <cuda_bf16.h>
#include <cstdint>

#define NN 50000
#define EE 800000
#define DD 512
#define NV4 (DD/4)

// ---------------- static scratch (no allocations allowed) ----------------
__device__ float g_s1[(size_t)NN * DD];
__device__ float g_s2[(size_t)NN * DD];
__device__ float g_m1[(size_t)NN * DD];
__device__ float g_m2[(size_t)NN * DD];
__device__ float g_l1[(size_t)NN * DD];
__device__ float g_l2[(size_t)NN * DD];
__device__ float g_z[(size_t)4 * NN * DD];  // z planes (plane 0 reused for cat out)
__device__ __nv_bfloat16 g_slh[(size_t)4 * NN * DD];  // A slots hi
__device__ __nv_bfloat16 g_sll[(size_t)4 * NN * DD];  // A slots lo
__device__ __nv_bfloat16 g_bh[2048 * 512];            // B transposed hi
__device__ __nv_bfloat16 g_bl[2048 * 512];            // B transposed lo
__device__ int   g_deg[NN];
__device__ int   g_rowp[NN + 1];
__device__ int   g_cur[NN];
__device__ int   g_csrc[EE];
__device__ float g_invdeg[NN];
__device__ float g_csum[4 * DD];
__device__ float g_csqr[4 * DD];
__device__ float g_scale[4 * DD];
__device__ float g_shift[4 * DD];

// ---------------- PTX helpers (sm_80-generic only) ----------------
__device__ __forceinline__ uint32_t smem_u32(const void* p) {
    uint32_t a;
    asm("{ .reg .u64 t; cvta.to.shared.u64 t, %1; cvt.u32.u64 %0, t; }" : "=r"(a) : "l"(p));
    return a;
}
__device__ __forceinline__ void cp_async16(uint32_t saddr, const void* gaddr, int sz) {
    asm volatile("cp.async.cg.shared.global [%0], [%1], 16, %2;"
                 :: "r"(saddr), "l"(gaddr), "r"(sz));
}
__device__ __forceinline__ void cp_commit() {
    asm volatile("cp.async.commit_group;");
}
template <int N>
__device__ __forceinline__ void cp_wait() {
    asm volatile("cp.async.wait_group %0;" :: "n"(N));
}
__device__ __forceinline__ void ldsm_x4(uint32_t& r0, uint32_t& r1, uint32_t& r2,
                                        uint32_t& r3, uint32_t addr) {
    asm volatile("ldmatrix.sync.aligned.m8n8.x4.shared.b16 {%0,%1,%2,%3}, [%4];"
                 : "=r"(r0), "=r"(r1), "=r"(r2), "=r"(r3) : "r"(addr));
}
__device__ __forceinline__ void mma_bf16(float* c, const uint32_t* a, const uint32_t* b) {
    asm volatile(
        "mma.sync.aligned.m16n8k16.row.col.f32.bf16.bf16.f32 "
        "{%0,%1,%2,%3}, {%4,%5,%6,%7}, {%8,%9}, {%0,%1,%2,%3};"
        : "+f"(c[0]), "+f"(c[1]), "+f"(c[2]), "+f"(c[3])
        : "r"(a[0]), "r"(a[1]), "r"(a[2]), "r"(a[3]), "r"(b[0]), "r"(b[1]));
}

__device__ __forceinline__ void split2(float x, float y, uint32_t& hi, uint32_t& lo) {
    __nv_bfloat162 h = __floats2bfloat162_rn(x, y);
    float rx = x - __bfloat162float(__low2bfloat16(h));
    float ry = y - __bfloat162float(__high2bfloat16(h));
    __nv_bfloat162 l = __floats2bfloat162_rn(rx, ry);
    hi = *(uint32_t*)&h;
    lo = *(uint32_t*)&l;
}

// ---------------- CSR build ----------------
__global__ void k_count(const int* __restrict__ dst, int E) {
    int e = blockIdx.x * blockDim.x + threadIdx.x;
    if (e < E) atomicAdd(&g_deg[dst[e]], 1);
}

__global__ void k_scan(int M) {
    __shared__ int sh[1024];
    __shared__ int running;
    if (threadIdx.x == 0) running = 0;
    __syncthreads();
    for (int base = 0; base < M; base += 1024) {
        int i = base + threadIdx.x;
        int v = (i < M) ? g_deg[i] : 0;
        sh[threadIdx.x] = v;
        __syncthreads();
        for (int off = 1; off < 1024; off <<= 1) {
            int t = 0;
            if ((int)threadIdx.x >= off) t = sh[threadIdx.x - off];
            __syncthreads();
            sh[threadIdx.x] += t;
            __syncthreads();
        }
        int incl = sh[threadIdx.x];
        int excl = running + incl - v;
        if (i < M) {
            g_rowp[i] = excl;
            g_cur[i] = excl;
            g_invdeg[i] = 1.0f / (float)(v > 1 ? v : 1);
        }
        __syncthreads();
        if (threadIdx.x == 0) running += sh[1023];
        __syncthreads();
    }
    if (threadIdx.x == 0) g_rowp[M] = running;
}

__global__ void k_scatter(const int* __restrict__ src, const int* __restrict__ dst, int E) {
    int e = blockIdx.x * blockDim.x + threadIdx.x;
    if (e < E) {
        int d = dst[e];
        int p = atomicAdd(&g_cur[d], 1);
        g_csrc[p] = src[e];
    }
}

// ------- aggregation: one block per node; writes bf16 hi/lo to slots 1,2 -------
__global__ void k_aggregate(const float* __restrict__ X, int M) {
    int nid = blockIdx.x;
    int t = threadIdx.x;
    int beg = g_rowp[nid], end = g_rowp[nid + 1];
    float4 s = make_float4(0.f, 0.f, 0.f, 0.f);
    float4 m = make_float4(-3.4e38f, -3.4e38f, -3.4e38f, -3.4e38f);
    const float4* Xb = (const float4*)X;
    for (int e = beg; e < end; e++) {
        int r = __ldg(&g_csrc[e]);
        float4 v = __ldg(Xb + (size_t)r * NV4 + t);
        s.x += v.x; s.y += v.y; s.z += v.z; s.w += v.w;
        m.x = fmaxf(m.x, v.x); m.y = fmaxf(m.y, v.y);
        m.z = fmaxf(m.z, v.z); m.w = fmaxf(m.w, v.w);
    }
    if (beg == end) m = make_float4(0.f, 0.f, 0.f, 0.f);
    size_t base = (size_t)nid * 256 + t * 2;  // in bf16x2 units
    uint32_t* sh1 = (uint32_t*)(g_slh + (size_t)1 * NN * DD);
    uint32_t* sl1 = (uint32_t*)(g_sll + (size_t)1 * NN * DD);
    uint32_t* sh2 = (uint32_t*)(g_slh + (size_t)2 * NN * DD);
    uint32_t* sl2 = (uint32_t*)(g_sll + (size_t)2 * NN * DD);
    uint32_t h, l;
    split2(s.x, s.y, h, l); sh1[base] = h; sl1[base] = l;
    split2(s.z, s.w, h, l); sh1[base + 1] = h; sl1[base + 1] = l;
    split2(m.x, m.y, h, l); sh2[base] = h; sl2[base] = l;
    split2(m.z, m.w, h, l); sh2[base + 1] = h; sl2[base + 1] = l;
}

// ---------------- split fp32 state into bf16 hi/lo slot ----------------
__global__ void k_split(const float* __restrict__ X, int slot, int M) {
    int idx = blockIdx.x * blockDim.x + threadIdx.x;
    int total = M * NV4;
    if (idx >= total) return;
    float4 v = ((const float4*)X)[idx];
    uint32_t* sh = (uint32_t*)(g_slh + (size_t)slot * NN * DD);
    uint32_t* sl = (uint32_t*)(g_sll + (size_t)slot * NN * DD);
    uint32_t h, l;
    split2(v.x, v.y, h, l); sh[idx * 2] = h; sl[idx * 2] = l;
    split2(v.z, v.w, h, l); sh[idx * 2 + 1] = h; sl[idx * 2 + 1] = l;
}

// ------ weight prep: transpose [K][N]->[N][K] + bf16 hi/lo split ------
__global__ void k_prep(const float* __restrict__ W, int K, int N) {
    __shared__ float t[32][33];
    const float* Wp = W + (size_t)blockIdx.z * K * N;
    __nv_bfloat16* oh = g_bh + (size_t)blockIdx.z * K * N;
    __nv_bfloat16* ol = g_bl + (size_t)blockIdx.z * K * N;
    int k0 = blockIdx.x * 32;
    int n0 = blockIdx.y * 32;
    int tx = threadIdx.x & 31, ty = threadIdx.x >> 5;
    for (int r = ty; r < 32; r += 8)
        t[r][tx] = __ldg(Wp + (size_t)(k0 + r) * N + n0 + tx);
    __syncthreads();
    for (int r = ty; r < 32; r += 8) {
        float w = t[tx][r];
        __nv_bfloat16 hb = __float2bfloat16_rn(w);
        float lof = w - __bfloat162float(hb);
        size_t o = (size_t)(n0 + r) * K + k0 + tx;
        oh[o] = hb;
        ol[o] = __float2bfloat16_rn(lof);
    }
}

// ---------------- bf16x3 mma.sync GEMM ----------------
// CTA 128x256, 16 warps (4m x 4n), warp 32x64, BK=32 double-buffered cp.async.
// mode 0: z[plane] = A_slot @ B[plane] (K=512), plane=blockIdx.z, slots {0,1,1,2}
// mode 1: z[0]     = [slot0|slot1|slot2|slot3] @ catB (K=2048)
#define APLANE 10240                       // 128 rows * 80B
#define BPLANE 20480                       // 256 rows * 80B
#define STAGEB (2 * APLANE + 2 * BPLANE)   // 61440
#define SMEM_GEMM (2 * STAGEB)             // 122880

__global__ void __launch_bounds__(512, 1)
k_gemm_mma(const float* __restrict__ bias, int M, int mode) {
    extern __shared__ char smem[];
    uint32_t sbase = smem_u32(smem);
    const int tid = threadIdx.x;
    const int wid = tid >> 5, lane = tid & 31;
    const int wm = wid & 3, wn = wid >> 2;
    const int rowBase = blockIdx.x * 128;
    const int colBase = blockIdx.y * 256;
    const int plane = blockIdx.z;

    const int K = (mode == 0) ? 512 : 2048;
    const int nStages = K / 32;
    const int bK = (mode == 0) ? 512 : 2048;
    const size_t bOff = (mode == 0) ? (size_t)plane * 512 * 512 : 0;

    auto loadA = [&](int s) {
        int slot, kin;
        if (mode == 0) {
            slot = (plane == 0) ? 0 : ((plane == 3) ? 2 : 1);
            kin = s * 32;
        } else {
            slot = s >> 4;
            kin = (s & 15) * 32;
        }
        const __nv_bfloat16* aH = g_slh + (size_t)slot * NN * DD;
        const __nv_bfloat16* aL = g_sll + (size_t)slot * NN * DD;
#pragma unroll
        for (int i = 0; i < 2; i++) {
            int idx = tid + 512 * i;
            int pl = idx >> 9, r = (idx >> 2) & 127, ch = idx & 3;
            int grow = rowBase + r;
            int gr = (grow < M) ? grow : (M - 1);
            const __nv_bfloat16* gp = (pl ? aL : aH) + (size_t)gr * 512 + kin + ch * 8;
            uint32_t dst = sbase + (s & 1) * STAGEB + pl * APLANE + r * 80 + ch * 16;
            cp_async16(dst, gp, (grow < M) ? 16 : 0);
        }
    };
    auto loadB = [&](int s) {
        int kin = s * 32;
#pragma unroll
        for (int i = 0; i < 4; i++) {
            int idx = tid + 512 * i;
            int pl = idx >> 10, r = (idx >> 2) & 255, ch = idx & 3;
            const __nv_bfloat16* gp =
                (pl ? g_bl : g_bh) + bOff + (size_t)(colBase + r) * bK + kin + ch * 8;
            uint32_t dst = sbase + (s & 1) * STAGEB + 2 * APLANE + pl * BPLANE + r * 80 + ch * 16;
            cp_async16(dst, gp, 16);
        }
    };

    float c[2][8][4];
#pragma unroll
    for (int mi = 0; mi < 2; mi++)
#pragma unroll
        for (int ni = 0; ni < 8; ni++)
#pragma unroll
            for (int j = 0; j < 4; j++) c[mi][ni][j] = 0.f;

    loadA(0); loadB(0); cp_commit();
    loadA(1); loadB(1); cp_commit();

    for (int s = 0; s < nStages; s++) {
        if (s + 1 < nStages) cp_wait<1>(); else cp_wait<0>();
        __syncthreads();
        uint32_t stg = sbase + (s & 1) * STAGEB;
        uint32_t aHiB = stg, aLoB = stg + APLANE;
        uint32_t bHiB = stg + 2 * APLANE, bLoB = bHiB + BPLANE;
#pragma unroll
        for (int kc = 0; kc < 2; kc++) {
            uint32_t ah[2][4], al[2][4];
#pragma unroll
            for (int mi = 0; mi < 2; mi++) {
                int row = wm * 32 + mi * 16 + (lane & 15);
                uint32_t off = (uint32_t)row * 80 + kc * 32 + (lane >> 4) * 16;
                ldsm_x4(ah[mi][0], ah[mi][1], ah[mi][2], ah[mi][3], aHiB + off);
                ldsm_x4(al[mi][0], al[mi][1], al[mi][2], al[mi][3], aLoB + off);
            }
#pragma unroll
            for (int np = 0; np < 4; np++) {
                int n = wn * 64 + np * 16 + ((lane >> 4) << 3) + (lane & 7);
                uint32_t off = (uint32_t)n * 80 + kc * 32 + ((lane >> 3) & 1) * 16;
                uint32_t h0, h1, h2, h3, l0, l1, l2, l3;
                ldsm_x4(h0, h1, h2, h3, bHiB + off);
                ldsm_x4(l0, l1, l2, l3, bLoB + off);
                uint32_t bh0[2] = {h0, h1}, bh1[2] = {h2, h3};
                uint32_t bl0[2] = {l0, l1}, bl1[2] = {l2, l3};
#pragma unroll
                for (int mi = 0; mi < 2; mi++) {
                    mma_bf16(c[mi][2 * np],     ah[mi], bh0);
                    mma_bf16(c[mi][2 * np],     al[mi], bh0);
                    mma_bf16(c[mi][2 * np],     ah[mi], bl0);
                    mma_bf16(c[mi][2 * np + 1], ah[mi], bh1);
                    mma_bf16(c[mi][2 * np + 1], al[mi], bh1);
                    mma_bf16(c[mi][2 * np + 1], ah[mi], bl1);
                }
            }
        }
        __syncthreads();
        if (s + 2 < nStages) { loadA(s + 2); loadB(s + 2); cp_commit(); }
    }

    // ---- epilogue ----
    const float* bp = bias + ((mode == 0) ? plane * DD : 0);
    float* zbase = (mode == 0) ? (g_z + (size_t)plane * M * DD) : g_z;
    const int doScale = (mode == 0 && plane == 2);
#pragma unroll
    for (int mi = 0; mi < 2; mi++) {
        int row0 = rowBase + wm * 32 + mi * 16 + (lane >> 2);
        int row1 = row0 + 8;
        float rs0 = 1.f, rs1 = 1.f;
        if (doScale) {
            if (row0 < M) rs0 = g_invdeg[row0];
            if (row1 < M) rs1 = g_invdeg[row1];
        }
#pragma unroll
        for (int ni = 0; ni < 8; ni++) {
            int col = colBase + wn * 64 + ni * 8 + (lane & 3) * 2;
            float b0 = __ldg(bp + col), b1 = __ldg(bp + col + 1);
            if (row0 < M) {
                float2 v;
                v.x = fmaf(c[mi][ni][0], rs0, b0);
                v.y = fmaf(c[mi][ni][1], rs0, b1);
                *(float2*)(zbase + (size_t)row0 * DD + col) = v;
            }
            if (row1 < M) {
                float2 v;
                v.x = fmaf(c[mi][ni][2], rs1, b0);
                v.y = fmaf(c[mi][ni][3], rs1, b1);
                *(float2*)(zbase + (size_t)row1 * DD + col) = v;
            }
        }
    }
}

// ---------------- per-(k,d) stats over nodes ----------------
__global__ void k_stats(int M) {
    int k = blockIdx.x >> 2;
    int d = ((blockIdx.x & 3) << 7) + threadIdx.x;
    int rows = (M + gridDim.y - 1) / gridDim.y;
    int r0 = blockIdx.y * rows;
    int r1 = r0 + rows; if (r1 > M) r1 = M;
    const float* p = g_z + ((size_t)k * M) * DD + d;
    float s = 0.f, q = 0.f;
    for (int r = r0; r < r1; r++) {
        float v = __ldg(p + (size_t)r * DD);
        s += v;
        q = fmaf(v, v, q);
    }
    atomicAdd(&g_csum[k * DD + d], s);
    atomicAdd(&g_csqr[k * DD + d], q);
}

__global__ void k_finalize(const float* __restrict__ gam, const float* __restrict__ bet,
                           int M, int P) {
    int i = blockIdx.x * blockDim.x + threadIdx.x;
    if (i < P * DD) {
        float inv = 1.0f / (float)M;
        float mu = g_csum[i] * inv;
        float var = g_csqr[i] * inv - mu * mu;
        float sc = rsqrtf(var + 1e-5f) * gam[i];
        g_scale[i] = sc;
        g_shift[i] = bet[i] - mu * sc;
    }
}

// ---------------- weighted relu combine over k ----------------
__global__ void k_combine(const float* __restrict__ w, float* __restrict__ out,
                          int M, int acc) {
    int idx = blockIdx.x * blockDim.x + threadIdx.x;
    int total = M * NV4;
    if (idx >= total) return;
    int dc = (idx % NV4) * 4;
    float4 r = acc ? ((const float4*)out)[idx] : make_float4(0.f, 0.f, 0.f, 0.f);
#pragma unroll
    for (int k = 0; k < 4; k++) {
        float wk = __ldg(w + k);
        float4 v = __ldg((const float4*)g_z + (size_t)k * M * NV4 + idx);
        float4 sc = *(const float4*)&g_scale[k * DD + dc];
        float4 sh = *(const float4*)&g_shift[k * DD + dc];
        float e;
        e = fmaxf(fmaf(v.x, sc.x, sh.x), 0.f); r.x = fmaf(wk, e, r.x);
        e = fmaxf(fmaf(v.y, sc.y, sh.y), 0.f); r.y = fmaf(wk, e, r.y);
        e = fmaxf(fmaf(v.z, sc.z, sh.z), 0.f); r.z = fmaf(wk, e, r.z);
        e = fmaxf(fmaf(v.w, sc.w, sh.w), 0.f); r.w = fmaf(wk, e, r.w);
    }
    ((float4*)out)[idx] = r;
}

// ---------------- final residual + BN + relu ----------------
__global__ void k_final(const float* __restrict__ h, float* __restrict__ out, int M) {
    int idx = blockIdx.x * blockDim.x + threadIdx.x;
    int total = M * NV4;
    if (idx >= total) return;
    int dc = (idx % NV4) * 4;
    float4 v = ((const float4*)g_z)[idx];
    float4 sc = *(const float4*)&g_scale[dc];
    float4 sh = *(const float4*)&g_shift[dc];
    float4 hv = ((const float4*)h)[idx];
    float4 o;
    o.x = hv.x + fmaxf(fmaf(v.x, sc.x, sh.x), 0.f);
    o.y = hv.y + fmaxf(fmaf(v.y, sc.y, sh.y), 0.f);
    o.z = hv.z + fmaxf(fmaf(v.z, sc.z, sh.z), 0.f);
    o.w = hv.w + fmaxf(fmaf(v.w, sc.w, sh.w), 0.f);
    ((float4*)out)[idx] = o;
}

// ---------------- host orchestration ----------------
static void run_mixed(const float* W4, const float* b4,
                      const float* g4, const float* be4, const float* w4,
                      float* outp, int acc, int M, void* sump, void* sqrp) {
    k_prep<<<dim3(16, 16, 4), 256>>>(W4, 512, 512);
    cudaMemsetAsync(sump, 0, 4 * DD * sizeof(float));
    cudaMemsetAsync(sqrp, 0, 4 * DD * sizeof(float));
    k_gemm_mma<<<dim3((M + 127) / 128, 2, 4), 512, SMEM_GEMM>>>(b4, M, 0);
    k_stats<<<dim3(16, 128), 128>>>(M);
    k_finalize<<<8, 256>>>(g4, be4, M, 4);
    k_combine<<<(M * NV4 + 255) / 256, 256>>>(w4, outp, M, acc);
}

extern "C" void kernel_launch(void* const* d_in, const int* in_sizes, int n_in,
                              void* d_out, int out_size) {
    const float* h    = (const float*)d_in[0];
    const int*   src  = (const int*)d_in[1];
    const int*   dst  = (const int*)d_in[2];
    const float* wf   = (const float*)d_in[3];
    const float* wm   = (const float*)d_in[4];
    const float* wl   = (const float*)d_in[5];
    const float* pfW  = (const float*)d_in[6];
    const float* pfb  = (const float*)d_in[7];
    const float* pfg  = (const float*)d_in[8];
    const float* pfB  = (const float*)d_in[9];
    const float* pmW  = (const float*)d_in[10];
    const float* pmb  = (const float*)d_in[11];
    const float* pmg  = (const float*)d_in[12];
    const float* pmB  = (const float*)d_in[13];
    const float* plW  = (const float*)d_in[14];
    const float* plb  = (const float*)d_in[15];
    const float* plg  = (const float*)d_in[16];
    const float* plB  = (const float*)d_in[17];
    const float* catW = (const float*)d_in[18];
    const float* catb = (const float*)d_in[19];
    const float* bng  = (const float*)d_in[20];
    const float* bnb  = (const float*)d_in[21];

    int M = in_sizes[0] / DD;
    int E = in_sizes[1];
    float* out = (float*)d_out;

    cudaFuncSetAttribute(k_gemm_mma, cudaFuncAttributeMaxDynamicSharedMemorySize, SMEM_GEMM);

    void *s1, *s2, *m1, *m2, *l1, *l2, *degp, *sump, *sqrp;
    cudaGetSymbolAddress(&s1, g_s1);
    cudaGetSymbolAddress(&s2, g_s2);
    cudaGetSymbolAddress(&m1, g_m1);
    cudaGetSymbolAddress(&m2, g_m2);
    cudaGetSymbolAddress(&l1, g_l1);
    cudaGetSymbolAddress(&l2, g_l2);
    cudaGetSymbolAddress(&degp, g_deg);
    cudaGetSymbolAddress(&sump, g_csum);
    cudaGetSymbolAddress(&sqrp, g_csqr);

    const size_t slabW = (size_t)4 * DD * DD;
    const size_t slabB = 4 * DD;
    const int nsp = (M * NV4 + 255) / 256;

    // CSR build (shared by all aggregations this launch)
    cudaMemsetAsync(degp, 0, M * sizeof(int));
    k_count<<<(E + 255) / 256, 256>>>(dst, E);
    k_scan<<<1, 1024>>>(M);
    k_scatter<<<(E + 255) / 256, 256>>>(src, dst, E);

    // first block: s1 = mixed(wf0, h); s2 = mixed(wf1, h) + mixed(wf2, s1)
    k_aggregate<<<M, 128>>>(h, M);
    k_split<<<nsp, 256>>>(h, 0, M);
    run_mixed(pfW + 0 * slabW, pfb + 0 * slabB, pfg + 0 * slabB, pfB + 0 * slabB,
              wf + 0, (float*)s1, 0, M, sump, sqrp);
    run_mixed(pfW + 1 * slabW, pfb + 1 * slabB, pfg + 1 * slabB, pfB + 1 * slabB,
              wf + 4, (float*)s2, 0, M, sump, sqrp);
    k_aggregate<<<M, 128>>>((const float*)s1, M);
    k_split<<<nsp, 256>>>((const float*)s1, 0, M);
    run_mixed(pfW + 2 * slabW, pfb + 2 * slabB, pfg + 2 * slabB,
              pfB + 2 * slabB, wf + 8, (float*)s2, 1, M, sump, sqrp);
    // middle (agg(s1) still in slots): m1 = mixed(wm0, s1)
    run_mixed(pmW + 0 * slabW, pmb + 0 * slabB, pmg + 0 * slabB,
              pmB + 0 * slabB, wm + 0, (float*)m1, 0, M, sump, sqrp);
    k_aggregate<<<M, 128>>>((const float*)s2, M);
    k_split<<<nsp, 256>>>((const float*)s2, 0, M);
    run_mixed(pmW + 1 * slabW, pmb + 1 * slabB, pmg + 1 * slabB,
              pmB + 1 * slabB, wm + 4, (float*)m2, 0, M, sump, sqrp);
    // last block
    k_aggregate<<<M, 128>>>((const float*)m1, M);
    k_split<<<nsp, 256>>>((const float*)m1, 0, M);
    run_mixed(plW + 0 * slabW, plb + 0 * slabB, plg + 0 * slabB,
              plB + 0 * slabB, wl + 0, (float*)l1, 0, M, sump, sqrp);
    run_mixed(plW + 2 * slabW, plb + 2 * slabB, plg + 2 * slabB,
              plB + 2 * slabB, wl + 8, (float*)l2, 0, M, sump, sqrp);
    k_aggregate<<<M, 128>>>((const float*)m2, M);
    k_split<<<nsp, 256>>>((const float*)m2, 0, M);
    run_mixed(plW + 1 * slabW, plb + 1 * slabB, plg + 1 * slabB,
              plB + 1 * slabB, wl + 4, (float*)l1, 1, M, sump, sqrp);
    run_mixed(plW + 3 * slabW, plb + 3 * slabB, plg + 3 * slabB,
              plB + 3 * slabB, wl + 12, (float*)l2, 1, M, sump, sqrp);
    k_aggregate<<<M, 128>>>((const float*)l1, M);
    k_split<<<nsp, 256>>>((const float*)l1, 0, M);
    run_mixed(plW + 4 * slabW, plb + 4 * slabB, plg + 4 * slabB,
              plB + 4 * slabB, wl + 16, (float*)l2, 1, M, sump, sqrp);

    // cat GEMM + batchnorm + relu + residual
    k_split<<<nsp, 256>>>((const float*)m1, 0, M);
    k_split<<<nsp, 256>>>((const float*)m2, 1, M);
    k_split<<<nsp, 256>>>((const float*)l1, 2, M);
    k_split<<<nsp, 256>>>((const float*)l2, 3, M);
    k_prep<<<dim3(64, 16, 1), 256>>>(catW, 2048, 512);
    k_gemm_mma<<<dim3((M + 127) / 128, 2, 1), 512, SMEM_GEMM>>>(catb, M, 1);
    cudaMemsetAsync(sump, 0, 4 * DD * sizeof(float));
    cudaMemsetAsync(sqrp, 0, 4 * DD * sizeof(float));
    k_stats<<<dim3(4, 128), 128>>>(M);
    k_finalize<<<8, 256>>>(bng, bnb, M, 1);
    k_final<<<nsp, 256>>>(h, out, M);
}